// round 17
// baseline (speedup 1.0000x reference)
#include <cuda_runtime.h>
#include <cuda_fp16.h>
#include <math.h>
#include <stdint.h>

#define N_NODES 100000
#define N_EDGES 6400000
#define THETA   1.0f
#define EQUIL_STEPS 100
#define REC_STEPS   200
#define TOTAL_STEPS (EQUIL_STEPS + REC_STEPS)
#define GRID_CTAS   148
#define CTA_THREADS 704            // 22 warps; 676 active node-threads
#define NPC         676            // slots per CTA (148*676 = 100048 >= 100000)
#define MAXDEG      160            // Poisson(64): P(deg>160) ~ 1e-23
#define NBIN        161
#define SMEM_BYTES  (N_NODES * 2)  // 200000 B fp16 state in shared memory
#define ALL_CHUNKS  (N_NODES * 2 / 16)               // 12500 x 16B
#define ELL_CTA_WORDS (NPC * MAXDEG)                 // 108160 words per CTA
#define ELL_TOTAL  ((size_t)GRID_CTAS * ELL_CTA_WORDS)   // 64 MB
#define GSTRIDE    (GRID_CTAS * CTA_THREADS)         // 104192

// ---------------- device scratch (sanctioned: __device__ globals) -------------
// Packed edge: bits[0:17)=src, bits[16:32)=fp16 weight (bit0 forced 0; bit16 shared).
// Group-of-4 ELL: edge j of slot r in CTA c at c*ELL_CTA_WORDS + (j>>2)*(NPC*4) + r*4 + (j&3)
__device__ unsigned g_ell[ELL_TOTAL];
__device__ int      g_deg[N_NODES];
__device__ int      g_cur[N_NODES];
__device__ int      g_pos[N_NODES];              // node -> global sorted position
__device__ int      g_pnode[GRID_CTAS * NPC];    // (cta,slot) -> node
__device__ int      g_bin[NBIN];                 // degree histogram / offsets
__device__ __half   g_state[2][N_NODES];
__device__ int      g_is64;
__device__ unsigned g_bar;

// ---------------- small helpers ------------------------------------------------
__device__ __forceinline__ unsigned smem_u32(const void* p) {
    unsigned a;
    asm("{ .reg .u64 t; cvta.to.shared.u64 t, %1; cvt.u32.u64 %0, t; }"
        : "=r"(a) : "l"(p));
    return a;
}
__device__ __forceinline__ void cp16(unsigned dst, const void* src) {
    asm volatile("cp.async.cg.shared.global [%0], [%1], 16;"
                 :: "r"(dst), "l"(src) : "memory");
}
// Software grid barrier; epoch is a cumulative count of barrier invocations.
__device__ __forceinline__ void grid_barrier(int tid, unsigned epoch) {
    __syncthreads();
    if (tid == 0) {
        __threadfence();
        atomicAdd(&g_bar, 1u);
        unsigned target = (unsigned)GRID_CTAS * epoch;
        while (*(volatile unsigned*)&g_bar < target) { }
        __threadfence();
    }
    __syncthreads();
}

// ---------------- dtype detection ---------------------------------------------
__global__ void detect_kernel(const int* __restrict__ ei32) {
    int all_zero = 1;
    for (int k = 0; k < 128; k++)
        if (ei32[2 * k + 1] != 0) { all_zero = 0; break; }
    g_is64 = all_zero;
}

// ---------------- preprocessing ------------------------------------------------
__global__ void zero_kernel() {
    int i = blockIdx.x * blockDim.x + threadIdx.x;
    if (i < N_NODES) { g_deg[i] = 0; g_cur[i] = 0; }
    if (i < NBIN) g_bin[i] = 0;
    if (i == 0) g_bar = 0u;
}

__global__ void ell_zero_kernel() {                  // zero pad => w=0 edges
    size_t i = (size_t)blockIdx.x * blockDim.x + threadIdx.x;
    uint4* p = (uint4*)g_ell;
    if (i < ELL_TOTAL / 4) p[i] = make_uint4(0u, 0u, 0u, 0u);
}

__device__ __forceinline__ int load_idx(const int* __restrict__ ei32,
                                        long long pos, int is64) {
    return is64 ? ei32[2 * pos] : ei32[pos];
}

__global__ void hist_kernel(const int* __restrict__ ei32) {
    long long i = blockIdx.x * blockDim.x + threadIdx.x;   // exact grid
    int is64 = g_is64;
    int d = load_idx(ei32, (long long)N_EDGES + i, is64);
    if ((unsigned)d < N_NODES) atomicAdd(&g_deg[d], 1);
}

__global__ void init_state_kernel(const float* __restrict__ x) {
    int i = blockIdx.x * blockDim.x + threadIdx.x;
    if (i < N_NODES) g_state[0][i] = __float2half_rn(x[i]);
}

// ---------------- persistent kernel: prologue (sort+scatter) + 300 steps -------
__device__ __forceinline__ float dec_edge(unsigned v, const __half* __restrict__ sh) {
    unsigned s = v & 0x1FFFFu;
    __half  w = __ushort_as_half((unsigned short)((v >> 16) & 0xFFFEu));
    return __half2float(w) * __half2float(sh[s]);
}

__global__ __launch_bounds__(CTA_THREADS, 1)
void sim_kernel(const int* __restrict__ ei32, const float* __restrict__ W,
                float* __restrict__ out) {
    extern __shared__ __half s_sh[];                 // 100000 halves = 200000 B
    __shared__ int sh_h[NBIN];
    __shared__ int sh_sc[NBIN];
    const int tid = threadIdx.x;
    const int cta = blockIdx.x;
    const unsigned sbase = smem_u32(s_sh);
    const int is64 = g_is64;
    unsigned epoch = 0;

    // ---- P1: global degree histogram (smem-privatized)
    for (int i = tid; i < NBIN; i += CTA_THREADS) sh_h[i] = 0;
    __syncthreads();
    for (int i = cta * CTA_THREADS + tid; i < N_NODES; i += GSTRIDE) {
        int d = g_deg[i]; if (d > MAXDEG) d = MAXDEG;
        atomicAdd(&sh_h[d], 1);
    }
    __syncthreads();
    for (int i = tid; i < NBIN; i += CTA_THREADS)
        if (sh_h[i]) atomicAdd(&g_bin[i], sh_h[i]);
    grid_barrier(tid, ++epoch);

    // ---- P2: exclusive prefix over 161 bins (CTA 0 only)
    if (cta == 0) {
        int own = 0;
        if (tid < NBIN) { own = g_bin[tid]; sh_sc[tid] = own; }
        __syncthreads();
        for (int off = 1; off < NBIN; off <<= 1) {
            int v = 0;
            if (tid < NBIN && tid >= off) v = sh_sc[tid - off];
            __syncthreads();
            if (tid < NBIN) sh_sc[tid] += v;
            __syncthreads();
        }
        if (tid < NBIN) g_bin[tid] = sh_sc[tid] - own;   // exclusive
    }
    grid_barrier(tid, ++epoch);

    // ---- P3: stratified placement: sorted position p -> CTA p%148, slot p/148
    for (int i = cta * CTA_THREADS + tid; i < N_NODES; i += GSTRIDE) {
        int d = g_deg[i]; if (d > MAXDEG) d = MAXDEG;
        int p = atomicAdd(&g_bin[d], 1);
        g_pos[i] = p;
        g_pnode[(p % GRID_CTAS) * NPC + (p / GRID_CTAS)] = i;
    }
    grid_barrier(tid, ++epoch);

    // ---- P4: scatter edges into packed group-of-4 ELL
    for (long long i = cta * CTA_THREADS + tid; i < N_EDGES; i += GSTRIDE) {
        int s = load_idx(ei32, i, is64);
        int d = load_idx(ei32, (long long)N_EDGES + i, is64);
        if ((unsigned)d >= N_NODES || (unsigned)s >= N_NODES) continue;
        int p = g_pos[d];
        int c = p % GRID_CTAS;
        int r = p / GRID_CTAS;
        int j = atomicAdd(&g_cur[d], 1);
        if (j < MAXDEG) {
            unsigned hw = (unsigned)__half_as_ushort(__float2half_rn(W[i]));
            hw = (hw + (hw & 1u)) & 0xFFFEu;         // round mantissa LSB away
            unsigned pk = (unsigned)s | (hw << 16);
            size_t idx = (size_t)c * ELL_CTA_WORDS
                       + (size_t)(j >> 2) * (NPC * 4) + (size_t)r * 4 + (j & 3);
            g_ell[idx] = pk;
        }
    }
    grid_barrier(tid, ++epoch);

    // ---- per-thread node binding
    const bool active = (tid < NPC) && (tid * GRID_CTAS + cta < N_NODES);
    int n = 0, groups = 0;
    if (active) {
        n = g_pnode[cta * NPC + tid];
        int d = g_deg[n]; if (d > MAXDEG) d = MAXDEG;
        groups = (d + 3) >> 2;
    }
    const uint4* __restrict__ e0 =
        (const uint4*)(g_ell + (size_t)cta * ELL_CTA_WORDS) + tid;

    // ---- 300 simulation steps
    for (int t = 0; t < TOTAL_STEPS; t++) {
        // stage full fp16 state into smem via cp.async (L2 path, no STS)
        const uint4* sv = (const uint4*)g_state[t & 1];
        for (int i = tid; i < ALL_CHUNKS; i += CTA_THREADS)
            cp16(sbase + i * 16, sv + i);
        asm volatile("cp.async.commit_group;" ::: "memory");
        asm volatile("cp.async.wait_group 0;" ::: "memory");
        __syncthreads();

        if (active) {
            const uint4* pe = e0;
            float a0 = 0.0f, a1 = 0.0f, a2 = 0.0f, a3 = 0.0f;
            int g = 0;
            for (; g + 2 <= groups; g += 2) {        // 8 edges, 2 LDG.128 in flight
                uint4 v0 = __ldg(pe);
                uint4 v1 = __ldg(pe + NPC);
                pe += 2 * NPC;
                a0 += dec_edge(v0.x, s_sh); a1 += dec_edge(v0.y, s_sh);
                a2 += dec_edge(v0.z, s_sh); a3 += dec_edge(v0.w, s_sh);
                a0 += dec_edge(v1.x, s_sh); a1 += dec_edge(v1.y, s_sh);
                a2 += dec_edge(v1.z, s_sh); a3 += dec_edge(v1.w, s_sh);
            }
            if (g < groups) {
                uint4 v = __ldg(pe);
                a0 += dec_edge(v.x, s_sh); a1 += dec_edge(v.y, s_sh);
                a2 += dec_edge(v.z, s_sh); a3 += dec_edge(v.w, s_sh);
            }
            float val = 1.0f / (1.0f + __expf(THETA - ((a0 + a1) + (a2 + a3))));
            g_state[(t + 1) & 1][n] = __float2half_rn(val);
            if (t >= EQUIL_STEPS)
                __stcs(out + (size_t)(t - EQUIL_STEPS) * N_NODES + n, val);
        }

        grid_barrier(tid, ++epoch);                  // all 148 CTAs co-resident
    }
}

// ---------------- launch --------------------------------------------------------
extern "C" void kernel_launch(void* const* d_in, const int* in_sizes, int n_in,
                              void* d_out, int out_size) {
    const float* x    = (const float*)d_in[0];   // (N_NODES, 1) f32
    const float* W    = (const float*)d_in[1];   // (N_EDGES,)   f32
    const int*   ei32 = (const int*)d_in[2];     // (2, N_EDGES) int32 view (int64 detected)
    float* out = (float*)d_out;                   // (REC_STEPS, N_NODES) f32

    cudaFuncSetAttribute(sim_kernel,
                         cudaFuncAttributeMaxDynamicSharedMemorySize, SMEM_BYTES);

    // 6 launches total; sim_kernel does sort+scatter prologue + 300 steps.
    detect_kernel<<<1, 1>>>(ei32);
    zero_kernel<<<(N_NODES + 255) / 256, 256>>>();
    ell_zero_kernel<<<(int)((ELL_TOTAL / 4 + 255) / 256), 256>>>();
    hist_kernel<<<N_EDGES / 256, 256>>>(ei32);
    init_state_kernel<<<(N_NODES + 255) / 256, 256>>>(x);
    sim_kernel<<<GRID_CTAS, CTA_THREADS, SMEM_BYTES>>>(ei32, W, out);
}